// round 7
// baseline (speedup 1.0000x reference)
#include <cuda_runtime.h>
#include <math.h>

#define Bn 2
#define Ln 2048
#define Dn 512
#define Nn 4096
#define Gn 64
#define Tn 512
#define EPSN 1e-12f
#define EPSW 1e-8f
#define NT 1024
#define NWS 32
#define CT 256
#define CE 8

// ---------------- scratch ----------------
__device__ __align__(256) float g_gn[Bn * Ln * Gn];
__device__ float g_norms[Bn * Ln];
__device__ float g_sim[Bn * Ln];
__device__ float g_coef[Bn * Ln];
__device__ int   g_lo[Bn * (Tn + 1)];

#define BARC() asm volatile("bar.sync 1, 256;" ::: "memory")

// ---------------- K0: dummy/init kernel (shifts ncu capture slot to k_merge) --
__global__ void k_init()
{
    int i = blockIdx.x * blockDim.x + threadIdx.x;
    if (i < Bn * Ln) g_coef[i] = 1.0f;
}

// ---------------- K1: g = x @ w^T, norms, gn (R1 exact: measured 27.6us) ------
__global__ void k_gn(const float* __restrict__ x, const float* __restrict__ w)
{
    int tok0 = blockIdx.x * 4;
    int warp = threadIdx.x >> 5;
    int lane = threadIdx.x & 31;

    float4 xr[4][4];
#pragma unroll
    for (int t = 0; t < 4; t++) {
        const float4* xp = (const float4*)(x + (size_t)(tok0 + t) * Dn);
#pragma unroll
        for (int q = 0; q < 4; q++) xr[t][q] = xp[lane + q * 32];
    }

    __shared__ float sg[4][Gn];
    __shared__ float snorm[4];

    for (int gg = 0; gg < 32; gg++) {
        int gi = warp * 32 + gg;
        const float4* wp = (const float4*)(w + (size_t)gi * Dn);
        float a0 = 0.f, a1 = 0.f, a2 = 0.f, a3 = 0.f;
#pragma unroll
        for (int q = 0; q < 4; q++) {
            float4 wv = wp[lane + q * 32];
            a0 += xr[0][q].x * wv.x + xr[0][q].y * wv.y + xr[0][q].z * wv.z + xr[0][q].w * wv.w;
            a1 += xr[1][q].x * wv.x + xr[1][q].y * wv.y + xr[1][q].z * wv.z + xr[1][q].w * wv.w;
            a2 += xr[2][q].x * wv.x + xr[2][q].y * wv.y + xr[2][q].z * wv.z + xr[2][q].w * wv.w;
            a3 += xr[3][q].x * wv.x + xr[3][q].y * wv.y + xr[3][q].z * wv.z + xr[3][q].w * wv.w;
        }
#pragma unroll
        for (int off = 16; off > 0; off >>= 1) {
            a0 += __shfl_down_sync(0xffffffffu, a0, off);
            a1 += __shfl_down_sync(0xffffffffu, a1, off);
            a2 += __shfl_down_sync(0xffffffffu, a2, off);
            a3 += __shfl_down_sync(0xffffffffu, a3, off);
        }
        if (lane == 0) { sg[0][gi] = a0; sg[1][gi] = a1; sg[2][gi] = a2; sg[3][gi] = a3; }
    }
    __syncthreads();

    if (threadIdx.x < 4) {
        int t = threadIdx.x;
        float ssum = 0.f;
        for (int gi = 0; gi < Gn; gi++) { float v = sg[t][gi]; ssum += v * v; }
        float nm = sqrtf(ssum);
        snorm[t] = nm;
        g_norms[tok0 + t] = nm;
    }
    __syncthreads();

    for (int idx = threadIdx.x; idx < 4 * Gn; idx += 64) {
        int t = idx >> 6, gi = idx & 63;
        g_gn[(size_t)(tok0 + t) * Gn + gi] = sg[t][gi] / fmaxf(snorm[t], EPSN);
    }
}

// ---------------- K1b: round-1 adjacent sims ----------------
__global__ void k_sim()
{
    int b = blockIdx.y;
    int warp = threadIdx.x >> 5;
    int lane = threadIdx.x & 31;
    int i = (blockIdx.x * 8 + warp) * 2 + (lane >> 4);
    int l = lane & 15;
    float d = 0.f;
    if (i < Ln - 1) {
        const float4* A = (const float4*)(g_gn + ((size_t)b * Ln + i) * Gn);
        float4 a = A[l], c = A[l + 16];
        d = a.x * c.x + a.y * c.y + a.z * c.z + a.w * c.w;
    }
    d += __shfl_down_sync(0xffffffffu, d, 8, 16);
    d += __shfl_down_sync(0xffffffffu, d, 4, 16);
    d += __shfl_down_sync(0xffffffffu, d, 2, 16);
    d += __shfl_down_sync(0xffffffffu, d, 1, 16);
    if (l == 0 && i < Ln - 1) g_sim[b * Ln + i] = d;
}

// ---------------- K2: merge plan (1 block per batch, closed-form matching) ----
// flags bit0: matched, bit1: selected, bit2: dirty
__global__ __launch_bounds__(NT) void k_merge()
{
    const int b = blockIdx.x;
    const int tid = threadIdx.x;
    const int wid = tid >> 5;
    const int lane = tid & 31;
    const int half = lane >> 4;
    const int l = lane & 15;

    __shared__ float s_norm[Ln];
    __shared__ float s_sim[Ln];
    __shared__ float s_coef[Ln];
    __shared__ unsigned short s_lo[Ln + 1];
    __shared__ unsigned char s_flag[Ln];
    __shared__ unsigned long long s_key[Ln];
    __shared__ int s_part[NWS];
    __shared__ int sh_n, sh_rem, sh_cnt;

    float* gnb   = g_gn + (size_t)b * Ln * Gn;
    float* coefb = g_coef + b * Ln;

    for (int i = tid; i < Ln; i += NT) {
        s_norm[i] = g_norms[b * Ln + i];
        s_sim[i]  = g_sim[b * Ln + i];
        s_lo[i]   = (unsigned short)i;
        s_flag[i] = 0;
        s_coef[i] = 1.0f;
    }
    if (tid == 0) { s_lo[Ln] = (unsigned short)Ln; sh_n = Ln; sh_rem = Ln - Tn; }
    __syncthreads();

    for (int round = 0; round < 24; round++) {
        int n = sh_n, rem = sh_rem;
        if (rem <= 0 || n < 2) break;
        int r_step = min(rem, n >> 1);

        // A) recompute dirty sims (all warps, half-warp cooperative)
        for (int bse = wid * 2; bse < n - 1; bse += NWS * 2) {
            int i = bse + half;
            bool valid = (i < n - 1) && (s_flag[i] & 4);
            float d = 0.f;
            if (valid) {
                const float4* Ap = (const float4*)(gnb + (size_t)s_lo[i] * Gn);
                const float4* Bp = (const float4*)(gnb + (size_t)s_lo[i + 1] * Gn);
                float4 a = Ap[l], c = Bp[l];
                d = a.x * c.x + a.y * c.y + a.z * c.z + a.w * c.w;
            }
            d += __shfl_down_sync(0xffffffffu, d, 8, 16);
            d += __shfl_down_sync(0xffffffffu, d, 4, 16);
            d += __shfl_down_sync(0xffffffffu, d, 2, 16);
            d += __shfl_down_sync(0xffffffffu, d, 1, 16);
            if (valid && l == 0) { s_sim[i] = d; s_flag[i] = (unsigned char)(s_flag[i] & ~4); }
        }
        __syncthreads();

        // B) closed-form greedy matching + count + selection (control threads)
        if (tid < CT) {
            int base = tid * CE;
            unsigned pre = 0, parF = 0, parB = 0;

            int run = -1;
#pragma unroll
            for (int e = 0; e < CE; e++) {
                int i = base + e;
                if (i < n - 1) {
                    bool bnd = (i == 0) || (s_sim[i - 1] < s_sim[i]);
                    if (bnd) run = i;
                    if (run < 0) pre |= (1u << e);
                    else if (((i - run) & 1) == 0) parF |= (1u << e);
                }
            }
            int incl = run;
#pragma unroll
            for (int off = 1; off < 32; off <<= 1) {
                int v = __shfl_up_sync(0xffffffffu, incl, off);
                if (lane >= off) incl = max(incl, v);
            }
            int excl = __shfl_up_sync(0xffffffffu, incl, 1);
            if (lane == 0) excl = -1;
            if (lane == 31) s_part[wid] = incl;
            BARC();
            {
                int carry = excl;
                for (int w2 = 0; w2 < wid; w2++) carry = max(carry, s_part[w2]);
                if (pre) {
#pragma unroll
                    for (int e = 0; e < CE; e++)
                        if ((pre >> e) & 1u) {
                            if ((((base + e) - carry) & 1) == 0) parF |= (1u << e);
                        }
                }
            }
            BARC();

            pre = 0; run = 0x7fffffff;
#pragma unroll
            for (int e = CE - 1; e >= 0; e--) {
                int i = base + e;
                if (i < n - 1) {
                    bool bnd = (i == n - 2) || (s_sim[i + 1] <= s_sim[i]);
                    if (bnd) run = i;
                    if (run == 0x7fffffff) pre |= (1u << e);
                    else if (((run - i) & 1) == 0) parB |= (1u << e);
                }
            }
            int sincl = run;
#pragma unroll
            for (int off = 1; off < 32; off <<= 1) {
                int v = __shfl_down_sync(0xffffffffu, sincl, off);
                if (lane + off < 32) sincl = min(sincl, v);
            }
            int sexcl = __shfl_down_sync(0xffffffffu, sincl, 1);
            if (lane == 31) sexcl = 0x7fffffff;
            if (lane == 0) s_part[wid] = sincl;
            BARC();
            {
                int carry = sexcl;
                for (int w2 = wid + 1; w2 < CT / 32; w2++) carry = min(carry, s_part[w2]);
                if (pre) {
#pragma unroll
                    for (int e = 0; e < CE; e++)
                        if ((pre >> e) & 1u) {
                            if (((carry - (base + e)) & 1) == 0) parB |= (1u << e);
                        }
                }
            }

            unsigned tk = parF & parB;
            int lm = 0;
#pragma unroll
            for (int e = 0; e < CE; e++) {
                int i = base + e;
                if (i < n - 1) {
                    unsigned t1 = (tk >> e) & 1u;
                    s_flag[i] = (unsigned char)((s_flag[i] & 4) | t1);
                    lm += (int)t1;
                }
            }
#pragma unroll
            for (int off = 16; off > 0; off >>= 1) lm += __shfl_down_sync(0xffffffffu, lm, off);
            BARC();
            if (lane == 0) s_part[wid] = lm;
            BARC();
            int m = 0;
            for (int w2 = 0; w2 < CT / 32; w2++) m += s_part[w2];
            int cnt = min(m, r_step);

            if (m > r_step) {
                int P = 1; while (P < n - 1) P <<= 1;
                for (int i = tid; i < P; i += CT) {
                    unsigned long long key = 0ull;
                    if (i < n - 1 && (s_flag[i] & 1)) {
                        unsigned u = __float_as_uint(s_sim[i]);
                        unsigned sk = (u & 0x80000000u) ? ~u : (u | 0x80000000u);
                        key = ((unsigned long long)sk << 16) | (unsigned)(Ln - 1 - i);
                    }
                    s_key[i] = key;
                }
                BARC();
                for (int kk = 2; kk <= P; kk <<= 1) {
                    for (int j = kk >> 1; j > 0; j >>= 1) {
                        for (int i = tid; i < P; i += CT) {
                            int ixj = i ^ j;
                            if (ixj > i) {
                                unsigned long long a = s_key[i], c = s_key[ixj];
                                bool dir = ((i & kk) == 0);
                                if (dir ? (a < c) : (a > c)) { s_key[i] = c; s_key[ixj] = a; }
                            }
                        }
                        BARC();
                    }
                }
                for (int r = tid; r < r_step; r += CT) {
                    int idx = Ln - 1 - (int)(s_key[r] & 0xFFFFull);
                    s_flag[idx] |= 2;
                }
            } else {
                for (int i = tid; i < n - 1; i += CT)
                    if (s_flag[i] & 1) s_flag[i] |= 2;
            }
            if (tid == 0) sh_cnt = cnt;
        }
        __syncthreads();
        int cnt = sh_cnt;

        // E) apply merges (all warps, half-warp cooperative; coef in shared)
        for (int bse = wid * 2; bse < n - 1; bse += NWS * 2) {
            int i = bse + half;
            bool valid = (i < n - 1) && (s_flag[i] & 2);
            float wi = 0.f, wj = 0.f, tot = 1.f;
            int ta = 0, tb = 0, tc = 0;
            float4 a = make_float4(0.f, 0.f, 0.f, 0.f);
            float4 c = a;
            float4* Ap = 0;
            if (valid) {
                wi = s_norm[i]; wj = s_norm[i + 1];
                tot = wi + wj + EPSW;
                ta = s_lo[i]; tb = s_lo[i + 1]; tc = s_lo[i + 2];
                Ap = (float4*)(gnb + (size_t)ta * Gn);
                const float4* Bp = (const float4*)(gnb + (size_t)tb * Gn);
                a = Ap[l]; c = Bp[l];
            }
            float mx = (wi * a.x + wj * c.x) / tot;
            float my = (wi * a.y + wj * c.y) / tot;
            float mz = (wi * a.z + wj * c.z) / tot;
            float mw = (wi * a.w + wj * c.w) / tot;
            float ssq = mx * mx + my * my + mz * mz + mw * mw;
            ssq += __shfl_xor_sync(0xffffffffu, ssq, 8, 16);
            ssq += __shfl_xor_sync(0xffffffffu, ssq, 4, 16);
            ssq += __shfl_xor_sync(0xffffffffu, ssq, 2, 16);
            ssq += __shfl_xor_sync(0xffffffffu, ssq, 1, 16);
            if (valid) {
                float inv = 1.f / fmaxf(sqrtf(ssq), EPSN);
                float4 o; o.x = mx * inv; o.y = my * inv; o.z = mz * inv; o.w = mw * inv;
                Ap[l] = o;
                float fa = wi / tot, fb = wj / tot;
                for (int t = ta + l; t < tb; t += 16) s_coef[t] *= fa;
                for (int t = tb + l; t < tc; t += 16) s_coef[t] *= fb;
                if (l == 0) {
                    s_norm[i] = (wi + wj) * 0.5f;
                    s_flag[i] |= 4;
                    if (i > 0) s_flag[i - 1] |= 4;
                }
            }
        }
        __syncthreads();

        // F) compaction (all threads, 2 elems each, warp scan + partials)
        {
            int b0 = tid * 2, b1 = tid * 2 + 1;
            int k0 = 0, k1 = 0;
            float n0 = 0.f, n1 = 0.f, si0 = 0.f, si1 = 0.f;
            unsigned short lo0 = 0, lo1 = 0;
            unsigned char f0 = 0, f1 = 0;
            if (b0 < n) {
                k0 = !(b0 > 0 && (s_flag[b0 - 1] & 2));
                if (k0) { n0 = s_norm[b0]; si0 = s_sim[b0]; lo0 = s_lo[b0]; f0 = s_flag[b0]; }
            }
            if (b1 < n) {
                k1 = !((s_flag[b1 - 1] & 2) != 0);
                if (k1) { n1 = s_norm[b1]; si1 = s_sim[b1]; lo1 = s_lo[b1]; f1 = s_flag[b1]; }
            }
            int loc = k0 + k1;
            int inc = loc;
#pragma unroll
            for (int off = 1; off < 32; off <<= 1) {
                int v = __shfl_up_sync(0xffffffffu, inc, off);
                if (lane >= off) inc += v;
            }
            int exc = inc - loc;
            if (lane == 31) s_part[wid] = inc;
            __syncthreads();
            int carry = 0;
            for (int w2 = 0; w2 < wid; w2++) carry += s_part[w2];
            int p0 = carry + exc;
            int p1 = p0 + k0;
            __syncthreads();
            if (k0) { s_norm[p0] = n0; s_sim[p0] = si0; s_lo[p0] = lo0; s_flag[p0] = f0; }
            if (k1) { s_norm[p1] = n1; s_sim[p1] = si1; s_lo[p1] = lo1; s_flag[p1] = f1; }
            if (tid == 0) { sh_n = n - cnt; sh_rem = rem - cnt; }
            __syncthreads();
            if (tid == 0) s_lo[n - cnt] = (unsigned short)Ln;
            __syncthreads();
        }
    }

    for (int i = tid; i < Ln; i += NT) coefb[i] = s_coef[i];
    for (int k = tid; k <= Tn; k += NT) g_lo[b * (Tn + 1) + k] = (int)s_lo[k];
}

// ---------------- K3: apply plan (R2 exact: measured 16.4us) ----------------
__global__ void k_apply(const float* __restrict__ x, const float* __restrict__ s,
                        float* __restrict__ out)
{
    int kslot = blockIdx.x;
    int chunk = blockIdx.y;
    int b = blockIdx.z;
    int lo = g_lo[b * (Tn + 1) + kslot];
    int hi = g_lo[b * (Tn + 1) + kslot + 1];
    int t4 = threadIdx.x;

    if (chunk == 0) {
        float4 acc = make_float4(0.f, 0.f, 0.f, 0.f);
#pragma unroll 2
        for (int t = lo; t < hi; t++) {
            float c = g_coef[b * Ln + t];
            float4 v = ((const float4*)(x + ((size_t)b * Ln + t) * Dn))[t4];
            acc.x += c * v.x; acc.y += c * v.y; acc.z += c * v.z; acc.w += c * v.w;
        }
        ((float4*)(out + ((size_t)b * Tn + kslot) * Dn))[t4] = acc;
    } else {
        int c0 = (chunk - 1) * 512;
        float4 acc = make_float4(0.f, 0.f, 0.f, 0.f);
#pragma unroll 2
        for (int t = lo; t < hi; t++) {
            float4 v = ((const float4*)(s + ((size_t)b * Ln + t) * Nn + c0))[t4];
            acc.x += v.x; acc.y += v.y; acc.z += v.z; acc.w += v.w;
        }
        ((float4*)(out + (size_t)Bn * Tn * Dn + ((size_t)b * Tn + kslot) * Nn + c0))[t4] = acc;
    }
}

// ---------------- launch ----------------
extern "C" void kernel_launch(void* const* d_in, const int* in_sizes, int n_in,
                              void* d_out, int out_size)
{
    const float* x = (const float*)d_in[0];
    const float* src = (const float*)d_in[1];
    const float* w = (const float*)d_in[2];
    float* out = (float*)d_out;

    k_init<<<8, 512>>>();                 // launch #0: shifts ncu capture slot
    k_gn<<<Bn * Ln / 4, 64>>>(x, w);      // #1
    k_sim<<<dim3(128, Bn), 256>>>();      // #2
    k_merge<<<Bn, NT>>>();                // #3  <- should now be the captured launch
    dim3 g3(Tn, 1 + Nn / 512, Bn);
    k_apply<<<g3, 128>>>(x, src, out);    // #4
}

// round 8
// speedup vs baseline: 1.6255x; 1.6255x over previous
#include <cuda_runtime.h>
#include <math.h>

#define Bn 2
#define Ln 2048
#define Dn 512
#define Nn 4096
#define Gn 64
#define Tn 512
#define EPSN 1e-12f
#define EPSW 1e-8f
#define CT 256
#define CE 8
#define RND 6

// ---------------- scratch ----------------
__device__ __align__(256) float g_gn[Bn * Ln * Gn];
__device__ float g_norms[Bn * Ln];
__device__ float g_sim[Bn * Ln];
__device__ float g_coef[Bn * Ln];
__device__ unsigned short g_slo[Bn][Ln + 1];

struct PairRec { int p, ta, tb, tc; float wi, wj; };
__device__ PairRec g_pairs[Bn][1024];
__device__ int g_edges[Bn][2048];
__device__ int g_pc[Bn], g_ec[Bn], g_nn[Bn], g_rm[Bn];

// ---------------- K0: init (coef=1, slot arrays, counters) ----------------
__global__ void k_init()
{
    int i = blockIdx.x * blockDim.x + threadIdx.x;
    if (i < Bn * Ln) {
        int b = i / Ln, t = i - b * Ln;
        g_coef[i] = 1.0f;
        g_slo[b][t] = (unsigned short)t;
        if (t == 0) {
            g_slo[b][Ln] = (unsigned short)Ln;
            g_nn[b] = Ln;
            g_rm[b] = Ln - Tn;
        }
    }
}

// ---------------- K1: g = x @ w^T, norms, gn (R1 exact) ----------------
__global__ void k_gn(const float* __restrict__ x, const float* __restrict__ w)
{
    int tok0 = blockIdx.x * 4;
    int warp = threadIdx.x >> 5;
    int lane = threadIdx.x & 31;

    float4 xr[4][4];
#pragma unroll
    for (int t = 0; t < 4; t++) {
        const float4* xp = (const float4*)(x + (size_t)(tok0 + t) * Dn);
#pragma unroll
        for (int q = 0; q < 4; q++) xr[t][q] = xp[lane + q * 32];
    }

    __shared__ float sg[4][Gn];
    __shared__ float snorm[4];

    for (int gg = 0; gg < 32; gg++) {
        int gi = warp * 32 + gg;
        const float4* wp = (const float4*)(w + (size_t)gi * Dn);
        float a0 = 0.f, a1 = 0.f, a2 = 0.f, a3 = 0.f;
#pragma unroll
        for (int q = 0; q < 4; q++) {
            float4 wv = wp[lane + q * 32];
            a0 += xr[0][q].x * wv.x + xr[0][q].y * wv.y + xr[0][q].z * wv.z + xr[0][q].w * wv.w;
            a1 += xr[1][q].x * wv.x + xr[1][q].y * wv.y + xr[1][q].z * wv.z + xr[1][q].w * wv.w;
            a2 += xr[2][q].x * wv.x + xr[2][q].y * wv.y + xr[2][q].z * wv.z + xr[2][q].w * wv.w;
            a3 += xr[3][q].x * wv.x + xr[3][q].y * wv.y + xr[3][q].z * wv.z + xr[3][q].w * wv.w;
        }
#pragma unroll
        for (int off = 16; off > 0; off >>= 1) {
            a0 += __shfl_down_sync(0xffffffffu, a0, off);
            a1 += __shfl_down_sync(0xffffffffu, a1, off);
            a2 += __shfl_down_sync(0xffffffffu, a2, off);
            a3 += __shfl_down_sync(0xffffffffu, a3, off);
        }
        if (lane == 0) { sg[0][gi] = a0; sg[1][gi] = a1; sg[2][gi] = a2; sg[3][gi] = a3; }
    }
    __syncthreads();

    if (threadIdx.x < 4) {
        int t = threadIdx.x;
        float ssum = 0.f;
        for (int gi = 0; gi < Gn; gi++) { float v = sg[t][gi]; ssum += v * v; }
        float nm = sqrtf(ssum);
        snorm[t] = nm;
        g_norms[tok0 + t] = nm;
    }
    __syncthreads();

    for (int idx = threadIdx.x; idx < 4 * Gn; idx += 64) {
        int t = idx >> 6, gi = idx & 63;
        g_gn[(size_t)(tok0 + t) * Gn + gi] = sg[t][gi] / fmaxf(snorm[t], EPSN);
    }
}

// ---------------- K1b: round-1 adjacent sims ----------------
__global__ void k_sim()
{
    int b = blockIdx.y;
    int warp = threadIdx.x >> 5;
    int lane = threadIdx.x & 31;
    int i = (blockIdx.x * 8 + warp) * 2 + (lane >> 4);
    int l = lane & 15;
    float d = 0.f;
    if (i < Ln - 1) {
        const float4* A = (const float4*)(g_gn + ((size_t)b * Ln + i) * Gn);
        float4 a = A[l], c = A[l + 16];
        d = a.x * c.x + a.y * c.y + a.z * c.z + a.w * c.w;
    }
    d += __shfl_down_sync(0xffffffffu, d, 8, 16);
    d += __shfl_down_sync(0xffffffffu, d, 4, 16);
    d += __shfl_down_sync(0xffffffffu, d, 2, 16);
    d += __shfl_down_sync(0xffffffffu, d, 1, 16);
    if (l == 0 && i < Ln - 1) g_sim[b * Ln + i] = d;
}

// ---------------- K2a: per-round control (scalar work only; 1 block/batch) ----
// flag bit0: matched, bit1: selected
__global__ __launch_bounds__(CT) void k_ctl()
{
    const int b = blockIdx.x;
    const int tid = threadIdx.x;
    const int wid = tid >> 5;
    const int lane = tid & 31;

    int n = g_nn[b], rem = g_rm[b];
    if (rem <= 0 || n < 2) {
        if (tid == 0) { g_pc[b] = 0; g_ec[b] = 0; }
        return;
    }
    int r_step = min(rem, n >> 1);

    __shared__ float s_sim[Ln];
    __shared__ float s_norm[Ln];
    __shared__ unsigned short s_lo[Ln + 1];
    __shared__ unsigned char s_flag[Ln];
    __shared__ unsigned char s_isPair[Ln];
    __shared__ unsigned long long s_key[Ln];
    __shared__ int s_part[8];
    __shared__ int sh_pc, sh_ec;

    for (int i = tid; i < n; i += CT) {
        s_sim[i]  = g_sim[b * Ln + i];
        s_norm[i] = g_norms[b * Ln + i];
        s_lo[i]   = g_slo[b][i];
    }
    if (tid == 0) { s_lo[n] = (unsigned short)Ln; sh_pc = 0; sh_ec = 0; }
    __syncthreads();

    // --- closed-form greedy matching ---
    int base = tid * CE;
    unsigned pre = 0, parF = 0, parB = 0;

    int run = -1;
#pragma unroll
    for (int e = 0; e < CE; e++) {
        int i = base + e;
        if (i < n - 1) {
            bool bnd = (i == 0) || (s_sim[i - 1] < s_sim[i]);
            if (bnd) run = i;
            if (run < 0) pre |= (1u << e);
            else if (((i - run) & 1) == 0) parF |= (1u << e);
        }
    }
    int incl = run;
#pragma unroll
    for (int off = 1; off < 32; off <<= 1) {
        int v = __shfl_up_sync(0xffffffffu, incl, off);
        if (lane >= off) incl = max(incl, v);
    }
    int excl = __shfl_up_sync(0xffffffffu, incl, 1);
    if (lane == 0) excl = -1;
    if (lane == 31) s_part[wid] = incl;
    __syncthreads();
    {
        int carry = excl;
        for (int w2 = 0; w2 < wid; w2++) carry = max(carry, s_part[w2]);
        if (pre) {
#pragma unroll
            for (int e = 0; e < CE; e++)
                if ((pre >> e) & 1u) {
                    if ((((base + e) - carry) & 1) == 0) parF |= (1u << e);
                }
        }
    }
    __syncthreads();

    pre = 0; run = 0x7fffffff;
#pragma unroll
    for (int e = CE - 1; e >= 0; e--) {
        int i = base + e;
        if (i < n - 1) {
            bool bnd = (i == n - 2) || (s_sim[i + 1] <= s_sim[i]);
            if (bnd) run = i;
            if (run == 0x7fffffff) pre |= (1u << e);
            else if (((run - i) & 1) == 0) parB |= (1u << e);
        }
    }
    int sincl = run;
#pragma unroll
    for (int off = 1; off < 32; off <<= 1) {
        int v = __shfl_down_sync(0xffffffffu, sincl, off);
        if (lane + off < 32) sincl = min(sincl, v);
    }
    int sexcl = __shfl_down_sync(0xffffffffu, sincl, 1);
    if (lane == 31) sexcl = 0x7fffffff;
    if (lane == 0) s_part[wid] = sincl;
    __syncthreads();
    {
        int carry = sexcl;
        for (int w2 = wid + 1; w2 < CT / 32; w2++) carry = min(carry, s_part[w2]);
        if (pre) {
#pragma unroll
            for (int e = 0; e < CE; e++)
                if ((pre >> e) & 1u) {
                    if (((carry - (base + e)) & 1) == 0) parB |= (1u << e);
                }
        }
    }

    unsigned tk = parF & parB;
    int lm = 0;
#pragma unroll
    for (int e = 0; e < CE; e++) {
        int i = base + e;
        if (i < n - 1) {
            unsigned t1 = (tk >> e) & 1u;
            s_flag[i] = (unsigned char)t1;
            lm += (int)t1;
        }
    }
#pragma unroll
    for (int off = 16; off > 0; off >>= 1) lm += __shfl_down_sync(0xffffffffu, lm, off);
    __syncthreads();
    if (lane == 0) s_part[wid] = lm;
    __syncthreads();
    int m = 0;
    for (int w2 = 0; w2 < CT / 32; w2++) m += s_part[w2];
    int cnt = min(m, r_step);

    // --- selection ---
    if (m > r_step) {
        int P = 1; while (P < n - 1) P <<= 1;
        for (int i = tid; i < P; i += CT) {
            unsigned long long key = 0ull;
            if (i < n - 1 && (s_flag[i] & 1)) {
                unsigned u = __float_as_uint(s_sim[i]);
                unsigned sk = (u & 0x80000000u) ? ~u : (u | 0x80000000u);
                key = ((unsigned long long)sk << 16) | (unsigned)(Ln - 1 - i);
            }
            s_key[i] = key;
        }
        __syncthreads();
        for (int kk = 2; kk <= P; kk <<= 1) {
            for (int j = kk >> 1; j > 0; j >>= 1) {
                for (int i = tid; i < P; i += CT) {
                    int ixj = i ^ j;
                    if (ixj > i) {
                        unsigned long long a = s_key[i], c = s_key[ixj];
                        bool dir = ((i & kk) == 0);
                        if (dir ? (a < c) : (a > c)) { s_key[i] = c; s_key[ixj] = a; }
                    }
                }
                __syncthreads();
            }
        }
        for (int r = tid; r < r_step; r += CT) {
            int idx = Ln - 1 - (int)(s_key[r] & 0xFFFFull);
            s_flag[idx] |= 2;
        }
    } else {
        for (int i = tid; i < n - 1; i += CT)
            if (s_flag[i] & 1) s_flag[i] |= 2;
    }
    __syncthreads();

    // --- compaction scan (keep = not 'second of a pair') + scatter + pairs ---
    int keepMask = 0, loc = 0;
#pragma unroll
    for (int e = 0; e < CE; e++) {
        int i = base + e;
        bool kp = (i < n) && !(i > 0 && (s_flag[i - 1] & 2));
        if (kp) { keepMask |= (1 << e); loc++; }
    }
    int inc = loc;
#pragma unroll
    for (int off = 1; off < 32; off <<= 1) {
        int v = __shfl_up_sync(0xffffffffu, inc, off);
        if (lane >= off) inc += v;
    }
    int exc = inc - loc;
    if (lane == 31) s_part[wid] = inc;
    __syncthreads();
    int carry = 0;
    for (int w2 = 0; w2 < wid; w2++) carry += s_part[w2];
    int p = carry + exc;
#pragma unroll
    for (int e = 0; e < CE; e++) {
        if ((keepMask >> e) & 1) {
            int i = base + e;
            bool isSel = (i < n - 1) && (s_flag[i] & 2);
            float wi2 = s_norm[i];
            g_norms[b * Ln + p] = isSel ? (wi2 + s_norm[i + 1]) * 0.5f : wi2;
            g_sim[b * Ln + p]   = s_sim[i];
            g_slo[b][p]         = s_lo[i];
            s_isPair[p] = isSel ? 1 : 0;
            if (isSel) {
                int k = atomicAdd(&sh_pc, 1);
                PairRec pr;
                pr.p = p; pr.ta = s_lo[i]; pr.tb = s_lo[i + 1]; pr.tc = s_lo[i + 2];
                pr.wi = wi2; pr.wj = s_norm[i + 1];
                g_pairs[b][k] = pr;
            }
            p++;
        }
    }
    __syncthreads();

    // --- dirty-edge emission ---
    int n_new = n - cnt;
    int pc = sh_pc;
    for (int k = tid; k < pc; k += CT) {
        int pp = g_pairs[b][k].p;
        if (pp + 1 < n_new) g_edges[b][atomicAdd(&sh_ec, 1)] = pp;
        if (pp > 0 && !s_isPair[pp - 1]) g_edges[b][atomicAdd(&sh_ec, 1)] = pp - 1;
    }
    __syncthreads();

    if (tid == 0) {
        g_slo[b][n_new] = (unsigned short)Ln;
        g_nn[b] = n_new;
        g_rm[b] = rem - cnt;
        g_pc[b] = pc;
        g_ec[b] = sh_ec;
    }
}

// ---------------- K2b: apply selected pair merges (full grid) ----------------
__global__ __launch_bounds__(256) void k_pairA()
{
    int b = blockIdx.y;
    int hw = blockIdx.x * 16 + (threadIdx.x >> 4);
    int l = threadIdx.x & 15;
    int cnt = g_pc[b];
    bool valid = hw < cnt;

    float* gnb = g_gn + (size_t)b * Ln * Gn;
    int ta = 0, tb = 0, tc = 0;
    float wi = 0.f, wj = 0.f, tot = 1.f;
    float4 a = make_float4(0.f, 0.f, 0.f, 0.f);
    float4 c = a;
    float4* Ap = 0;
    if (valid) {
        PairRec pr = g_pairs[b][hw];
        ta = pr.ta; tb = pr.tb; tc = pr.tc; wi = pr.wi; wj = pr.wj;
        tot = wi + wj + EPSW;
        Ap = (float4*)(gnb + (size_t)ta * Gn);
        a = Ap[l];
        c = ((const float4*)(gnb + (size_t)tb * Gn))[l];
    }
    float mx = (wi * a.x + wj * c.x) / tot;
    float my = (wi * a.y + wj * c.y) / tot;
    float mz = (wi * a.z + wj * c.z) / tot;
    float mw = (wi * a.w + wj * c.w) / tot;
    float ssq = mx * mx + my * my + mz * mz + mw * mw;
    ssq += __shfl_xor_sync(0xffffffffu, ssq, 8, 16);
    ssq += __shfl_xor_sync(0xffffffffu, ssq, 4, 16);
    ssq += __shfl_xor_sync(0xffffffffu, ssq, 2, 16);
    ssq += __shfl_xor_sync(0xffffffffu, ssq, 1, 16);
    if (valid) {
        float inv = 1.f / fmaxf(sqrtf(ssq), EPSN);
        float4 o; o.x = mx * inv; o.y = my * inv; o.z = mz * inv; o.w = mw * inv;
        Ap[l] = o;
        float fa = wi / tot, fb = wj / tot;
        float* cb = g_coef + b * Ln;
        for (int t = ta + l; t < tb; t += 16) cb[t] *= fa;
        for (int t = tb + l; t < tc; t += 16) cb[t] *= fb;
    }
}

// ---------------- K2c: recompute dirty-edge sims (full grid) ----------------
__global__ __launch_bounds__(256) void k_pairB()
{
    int b = blockIdx.y;
    int hw = blockIdx.x * 16 + (threadIdx.x >> 4);
    int l = threadIdx.x & 15;
    int ec = g_ec[b];
    bool valid = hw < ec;

    const float* gnb = g_gn + (size_t)b * Ln * Gn;
    int pos = 0;
    float d = 0.f;
    if (valid) {
        pos = g_edges[b][hw];
        int tA = g_slo[b][pos], tB = g_slo[b][pos + 1];
        float4 a = ((const float4*)(gnb + (size_t)tA * Gn))[l];
        float4 c = ((const float4*)(gnb + (size_t)tB * Gn))[l];
        d = a.x * c.x + a.y * c.y + a.z * c.z + a.w * c.w;
    }
    d += __shfl_down_sync(0xffffffffu, d, 8, 16);
    d += __shfl_down_sync(0xffffffffu, d, 4, 16);
    d += __shfl_down_sync(0xffffffffu, d, 2, 16);
    d += __shfl_down_sync(0xffffffffu, d, 1, 16);
    if (valid && l == 0) g_sim[b * Ln + pos] = d;
}

// ---------------- K3: apply plan (bandwidth-bound) ----------------
__global__ void k_apply(const float* __restrict__ x, const float* __restrict__ s,
                        float* __restrict__ out)
{
    int kslot = blockIdx.x;
    int chunk = blockIdx.y;
    int b = blockIdx.z;
    int lo = g_slo[b][kslot];
    int hi = g_slo[b][kslot + 1];
    int t4 = threadIdx.x;

    if (chunk == 0) {
        float4 acc = make_float4(0.f, 0.f, 0.f, 0.f);
#pragma unroll 2
        for (int t = lo; t < hi; t++) {
            float c = g_coef[b * Ln + t];
            float4 v = ((const float4*)(x + ((size_t)b * Ln + t) * Dn))[t4];
            acc.x += c * v.x; acc.y += c * v.y; acc.z += c * v.z; acc.w += c * v.w;
        }
        ((float4*)(out + ((size_t)b * Tn + kslot) * Dn))[t4] = acc;
    } else {
        int c0 = (chunk - 1) * 512;
        float4 acc = make_float4(0.f, 0.f, 0.f, 0.f);
#pragma unroll 2
        for (int t = lo; t < hi; t++) {
            float4 v = ((const float4*)(s + ((size_t)b * Ln + t) * Nn + c0))[t4];
            acc.x += v.x; acc.y += v.y; acc.z += v.z; acc.w += v.w;
        }
        ((float4*)(out + (size_t)Bn * Tn * Dn + ((size_t)b * Tn + kslot) * Nn + c0))[t4] = acc;
    }
}

// ---------------- launch ----------------
extern "C" void kernel_launch(void* const* d_in, const int* in_sizes, int n_in,
                              void* d_out, int out_size)
{
    const float* x = (const float*)d_in[0];
    const float* src = (const float*)d_in[1];
    const float* w = (const float*)d_in[2];
    float* out = (float*)d_out;

    k_init<<<8, 512>>>();                     // #0
    k_gn<<<Bn * Ln / 4, 64>>>(x, w);          // #1
    k_sim<<<dim3(128, Bn), 256>>>();          // #2
    for (int r = 0; r < RND; r++) {
        k_ctl<<<Bn, CT>>>();                  // #3 (round 1) -> ncu capture slot
        k_pairA<<<dim3(64, Bn), 256>>>();
        k_pairB<<<dim3(128, Bn), 256>>>();
    }
    dim3 g3(Tn, 1 + Nn / 512, Bn);
    k_apply<<<g3, 128>>>(x, src, out);
}

// round 9
// speedup vs baseline: 1.6259x; 1.0003x over previous
#include <cuda_runtime.h>
#include <math.h>

#define Bn 2
#define Ln 2048
#define Dn 512
#define Nn 4096
#define Gn 64
#define Tn 512
#define EPSN 1e-12f
#define EPSW 1e-8f
#define CT 256
#define CE 8
#define RND 6

// ---------------- scratch ----------------
__device__ __align__(256) float g_gn[Bn * Ln * Gn];
__device__ float g_norms[Bn * Ln];
__device__ float g_sim[Bn * Ln];
__device__ float g_coef[Bn * Ln];
__device__ unsigned short g_slo[Bn][Ln + 1];

struct PairRec { int p, ta, tb, tc; float wi, wj; };
__device__ PairRec g_pairs[Bn][1024];
__device__ int g_edges[Bn][2048];
__device__ int g_pc[Bn], g_ec[Bn], g_nn[Bn], g_rm[Bn];

// ---------------- K0: init ----------------
__global__ void k_init()
{
    int i = blockIdx.x * blockDim.x + threadIdx.x;
    if (i < Bn * Ln) {
        int b = i / Ln, t = i - b * Ln;
        g_coef[i] = 1.0f;
        g_slo[b][t] = (unsigned short)t;
        if (t == 0) {
            g_slo[b][Ln] = (unsigned short)Ln;
            g_nn[b] = Ln;
            g_rm[b] = Ln - Tn;
        }
    }
}

// ---------------- K1: g = x @ w^T, norms, gn — smem-tiled GEMM ----------------
// 128 blocks x 256 threads, 32 tokens/block, K-tiles of 64, w transposed in smem.
// Register tile: 2 tokens x 4 groups per thread.
__global__ __launch_bounds__(256) void k_gn(const float* __restrict__ x,
                                            const float* __restrict__ w)
{
    const int tid = threadIdx.x;
    const int tok0 = blockIdx.x * 32;
    const int gt = tid & 15;     // group-thread: groups gt*4 .. gt*4+3
    const int tt = tid >> 4;     // token-thread: tokens tt, tt+16

    __shared__ float xs[32][68];    // x tile  [tok][k]   (stride 68: f4-aligned, low conflict)
    __shared__ float wsT[64][68];   // w tile transposed [k][grp]
    __shared__ float psum[4][32];
    __shared__ float snorm[32];

    float acc0x = 0.f, acc0y = 0.f, acc0z = 0.f, acc0w = 0.f;
    float acc1x = 0.f, acc1y = 0.f, acc1z = 0.f, acc1w = 0.f;

    const int xrow = tid >> 3;          // 0..31
    const int xf4  = tid & 7;           // + q*8, q=0..1
    const int wrow = tid >> 2;          // group row 0..63
    const int wf4  = tid & 3;           // + q*4, q=0..3

    for (int kt = 0; kt < 8; kt++) {
        // load x tile: 32 x 64 floats
        {
            const float4* xg = (const float4*)(x + (size_t)(tok0 + xrow) * Dn + kt * 64);
            float4* xsr = (float4*)&xs[xrow][0];
#pragma unroll
            for (int q = 0; q < 2; q++) xsr[xf4 + q * 8] = xg[xf4 + q * 8];
        }
        // load w tile transposed: 64 grp x 64 k -> wsT[k][grp]
        {
            const float4* wg = (const float4*)(w + (size_t)wrow * Dn + kt * 64);
#pragma unroll
            for (int q = 0; q < 4; q++) {
                float4 v = wg[wf4 + q * 4];
                int kb = (wf4 + q * 4) * 4;
                wsT[kb + 0][wrow] = v.x;
                wsT[kb + 1][wrow] = v.y;
                wsT[kb + 2][wrow] = v.z;
                wsT[kb + 3][wrow] = v.w;
            }
        }
        __syncthreads();

#pragma unroll
        for (int k4 = 0; k4 < 16; k4++) {
            float4 xv0 = *(const float4*)&xs[tt][k4 * 4];
            float4 xv1 = *(const float4*)&xs[tt + 16][k4 * 4];
#pragma unroll
            for (int e = 0; e < 4; e++) {
                float4 wv = *(const float4*)&wsT[k4 * 4 + e][gt * 4];
                float x0 = (e == 0) ? xv0.x : (e == 1) ? xv0.y : (e == 2) ? xv0.z : xv0.w;
                float x1 = (e == 0) ? xv1.x : (e == 1) ? xv1.y : (e == 2) ? xv1.z : xv1.w;
                acc0x += x0 * wv.x; acc0y += x0 * wv.y; acc0z += x0 * wv.z; acc0w += x0 * wv.w;
                acc1x += x1 * wv.x; acc1y += x1 * wv.y; acc1z += x1 * wv.z; acc1w += x1 * wv.w;
            }
        }
        __syncthreads();
    }

    // stage g into xs (reuse): sg[tok][grp]
    xs[tt][gt * 4 + 0] = acc0x;  xs[tt][gt * 4 + 1] = acc0y;
    xs[tt][gt * 4 + 2] = acc0z;  xs[tt][gt * 4 + 3] = acc0w;
    xs[tt + 16][gt * 4 + 0] = acc1x;  xs[tt + 16][gt * 4 + 1] = acc1y;
    xs[tt + 16][gt * 4 + 2] = acc1z;  xs[tt + 16][gt * 4 + 3] = acc1w;
    __syncthreads();

    // norms
    if (tid < 128) {
        int tok = tid & 31, p = tid >> 5;
        float s = 0.f;
#pragma unroll
        for (int gi = p * 16; gi < p * 16 + 16; gi++) { float v = xs[tok][gi]; s += v * v; }
        psum[p][tok] = s;
    }
    __syncthreads();
    if (tid < 32) {
        float ss = ((psum[0][tid] + psum[1][tid]) + psum[2][tid]) + psum[3][tid];
        float nm = sqrtf(ss);
        snorm[tid] = fmaxf(nm, EPSN);
        g_norms[tok0 + tid] = nm;
    }
    __syncthreads();

    // write gn (normalized), coalesced float4
    {
        int row = tid >> 3;
        float inv = 1.f / snorm[row];
        float4* dst = (float4*)(g_gn + (size_t)(tok0 + row) * Gn);
#pragma unroll
        for (int q = 0; q < 2; q++) {
            int f4 = (tid & 7) + q * 8;
            float4 v = *(const float4*)&xs[row][f4 * 4];
            v.x *= inv; v.y *= inv; v.z *= inv; v.w *= inv;
            dst[f4] = v;
        }
    }
}

// ---------------- K1b: round-1 adjacent sims ----------------
__global__ void k_sim()
{
    int b = blockIdx.y;
    int warp = threadIdx.x >> 5;
    int lane = threadIdx.x & 31;
    int i = (blockIdx.x * 8 + warp) * 2 + (lane >> 4);
    int l = lane & 15;
    float d = 0.f;
    if (i < Ln - 1) {
        const float4* A = (const float4*)(g_gn + ((size_t)b * Ln + i) * Gn);
        float4 a = A[l], c = A[l + 16];
        d = a.x * c.x + a.y * c.y + a.z * c.z + a.w * c.w;
    }
    d += __shfl_down_sync(0xffffffffu, d, 8, 16);
    d += __shfl_down_sync(0xffffffffu, d, 4, 16);
    d += __shfl_down_sync(0xffffffffu, d, 2, 16);
    d += __shfl_down_sync(0xffffffffu, d, 1, 16);
    if (l == 0 && i < Ln - 1) g_sim[b * Ln + i] = d;
}

// ---------------- K2a: per-round control (scalar work only) ----------------
__global__ __launch_bounds__(CT) void k_ctl()
{
    const int b = blockIdx.x;
    const int tid = threadIdx.x;
    const int wid = tid >> 5;
    const int lane = tid & 31;

    int n = g_nn[b], rem = g_rm[b];
    if (rem <= 0 || n < 2) {
        if (tid == 0) { g_pc[b] = 0; g_ec[b] = 0; }
        return;
    }
    int r_step = min(rem, n >> 1);

    __shared__ float s_sim[Ln];
    __shared__ float s_norm[Ln];
    __shared__ unsigned short s_lo[Ln + 1];
    __shared__ unsigned char s_flag[Ln];
    __shared__ unsigned char s_isPair[Ln];
    __shared__ unsigned long long s_key[Ln];
    __shared__ int s_part[8];
    __shared__ int sh_pc, sh_ec;

    for (int i = tid; i < n; i += CT) {
        s_sim[i]  = g_sim[b * Ln + i];
        s_norm[i] = g_norms[b * Ln + i];
        s_lo[i]   = g_slo[b][i];
    }
    if (tid == 0) { s_lo[n] = (unsigned short)Ln; sh_pc = 0; sh_ec = 0; }
    __syncthreads();

    int base = tid * CE;
    unsigned pre = 0, parF = 0, parB = 0;

    int run = -1;
#pragma unroll
    for (int e = 0; e < CE; e++) {
        int i = base + e;
        if (i < n - 1) {
            bool bnd = (i == 0) || (s_sim[i - 1] < s_sim[i]);
            if (bnd) run = i;
            if (run < 0) pre |= (1u << e);
            else if (((i - run) & 1) == 0) parF |= (1u << e);
        }
    }
    int incl = run;
#pragma unroll
    for (int off = 1; off < 32; off <<= 1) {
        int v = __shfl_up_sync(0xffffffffu, incl, off);
        if (lane >= off) incl = max(incl, v);
    }
    int excl = __shfl_up_sync(0xffffffffu, incl, 1);
    if (lane == 0) excl = -1;
    if (lane == 31) s_part[wid] = incl;
    __syncthreads();
    {
        int carry = excl;
        for (int w2 = 0; w2 < wid; w2++) carry = max(carry, s_part[w2]);
        if (pre) {
#pragma unroll
            for (int e = 0; e < CE; e++)
                if ((pre >> e) & 1u) {
                    if ((((base + e) - carry) & 1) == 0) parF |= (1u << e);
                }
        }
    }
    __syncthreads();

    pre = 0; run = 0x7fffffff;
#pragma unroll
    for (int e = CE - 1; e >= 0; e--) {
        int i = base + e;
        if (i < n - 1) {
            bool bnd = (i == n - 2) || (s_sim[i + 1] <= s_sim[i]);
            if (bnd) run = i;
            if (run == 0x7fffffff) pre |= (1u << e);
            else if (((run - i) & 1) == 0) parB |= (1u << e);
        }
    }
    int sincl = run;
#pragma unroll
    for (int off = 1; off < 32; off <<= 1) {
        int v = __shfl_down_sync(0xffffffffu, sincl, off);
        if (lane + off < 32) sincl = min(sincl, v);
    }
    int sexcl = __shfl_down_sync(0xffffffffu, sincl, 1);
    if (lane == 31) sexcl = 0x7fffffff;
    if (lane == 0) s_part[wid] = sincl;
    __syncthreads();
    {
        int carry = sexcl;
        for (int w2 = wid + 1; w2 < CT / 32; w2++) carry = min(carry, s_part[w2]);
        if (pre) {
#pragma unroll
            for (int e = 0; e < CE; e++)
                if ((pre >> e) & 1u) {
                    if (((carry - (base + e)) & 1) == 0) parB |= (1u << e);
                }
        }
    }

    unsigned tk = parF & parB;
    int lm = 0;
#pragma unroll
    for (int e = 0; e < CE; e++) {
        int i = base + e;
        if (i < n - 1) {
            unsigned t1 = (tk >> e) & 1u;
            s_flag[i] = (unsigned char)t1;
            lm += (int)t1;
        }
    }
#pragma unroll
    for (int off = 16; off > 0; off >>= 1) lm += __shfl_down_sync(0xffffffffu, lm, off);
    __syncthreads();
    if (lane == 0) s_part[wid] = lm;
    __syncthreads();
    int m = 0;
    for (int w2 = 0; w2 < CT / 32; w2++) m += s_part[w2];
    int cnt = min(m, r_step);

    if (m > r_step) {
        int P = 1; while (P < n - 1) P <<= 1;
        for (int i = tid; i < P; i += CT) {
            unsigned long long key = 0ull;
            if (i < n - 1 && (s_flag[i] & 1)) {
                unsigned u = __float_as_uint(s_sim[i]);
                unsigned sk = (u & 0x80000000u) ? ~u : (u | 0x80000000u);
                key = ((unsigned long long)sk << 16) | (unsigned)(Ln - 1 - i);
            }
            s_key[i] = key;
        }
        __syncthreads();
        for (int kk = 2; kk <= P; kk <<= 1) {
            for (int j = kk >> 1; j > 0; j >>= 1) {
                for (int i = tid; i < P; i += CT) {
                    int ixj = i ^ j;
                    if (ixj > i) {
                        unsigned long long a = s_key[i], c = s_key[ixj];
                        bool dir = ((i & kk) == 0);
                        if (dir ? (a < c) : (a > c)) { s_key[i] = c; s_key[ixj] = a; }
                    }
                }
                __syncthreads();
            }
        }
        for (int r = tid; r < r_step; r += CT) {
            int idx = Ln - 1 - (int)(s_key[r] & 0xFFFFull);
            s_flag[idx] |= 2;
        }
    } else {
        for (int i = tid; i < n - 1; i += CT)
            if (s_flag[i] & 1) s_flag[i] |= 2;
    }
    __syncthreads();

    int keepMask = 0, loc = 0;
#pragma unroll
    for (int e = 0; e < CE; e++) {
        int i = base + e;
        bool kp = (i < n) && !(i > 0 && (s_flag[i - 1] & 2));
        if (kp) { keepMask |= (1 << e); loc++; }
    }
    int inc = loc;
#pragma unroll
    for (int off = 1; off < 32; off <<= 1) {
        int v = __shfl_up_sync(0xffffffffu, inc, off);
        if (lane >= off) inc += v;
    }
    int exc = inc - loc;
    if (lane == 31) s_part[wid] = inc;
    __syncthreads();
    int carry = 0;
    for (int w2 = 0; w2 < wid; w2++) carry += s_part[w2];
    int p = carry + exc;
#pragma unroll
    for (int e = 0; e < CE; e++) {
        if ((keepMask >> e) & 1) {
            int i = base + e;
            bool isSel = (i < n - 1) && (s_flag[i] & 2);
            float wi2 = s_norm[i];
            g_norms[b * Ln + p] = isSel ? (wi2 + s_norm[i + 1]) * 0.5f : wi2;
            g_sim[b * Ln + p]   = s_sim[i];
            g_slo[b][p]         = s_lo[i];
            s_isPair[p] = isSel ? 1 : 0;
            if (isSel) {
                int k = atomicAdd(&sh_pc, 1);
                PairRec pr;
                pr.p = p; pr.ta = s_lo[i]; pr.tb = s_lo[i + 1]; pr.tc = s_lo[i + 2];
                pr.wi = wi2; pr.wj = s_norm[i + 1];
                g_pairs[b][k] = pr;
            }
            p++;
        }
    }
    __syncthreads();

    int n_new = n - cnt;
    int pc = sh_pc;
    for (int k = tid; k < pc; k += CT) {
        int pp = g_pairs[b][k].p;
        if (pp + 1 < n_new) g_edges[b][atomicAdd(&sh_ec, 1)] = pp;
        if (pp > 0 && !s_isPair[pp - 1]) g_edges[b][atomicAdd(&sh_ec, 1)] = pp - 1;
    }
    __syncthreads();

    if (tid == 0) {
        g_slo[b][n_new] = (unsigned short)Ln;
        g_nn[b] = n_new;
        g_rm[b] = rem - cnt;
        g_pc[b] = pc;
        g_ec[b] = sh_ec;
    }
}

// ---------------- K2b: apply selected pair merges (full grid) ----------------
__global__ __launch_bounds__(256) void k_pairA()
{
    int b = blockIdx.y;
    int hw = blockIdx.x * 16 + (threadIdx.x >> 4);
    int l = threadIdx.x & 15;
    int cnt = g_pc[b];
    bool valid = hw < cnt;

    float* gnb = g_gn + (size_t)b * Ln * Gn;
    int ta = 0, tb = 0, tc = 0;
    float wi = 0.f, wj = 0.f, tot = 1.f;
    float4 a = make_float4(0.f, 0.f, 0.f, 0.f);
    float4 c = a;
    float4* Ap = 0;
    if (valid) {
        PairRec pr = g_pairs[b][hw];
        ta = pr.ta; tb = pr.tb; tc = pr.tc; wi = pr.wi; wj = pr.wj;
        tot = wi + wj + EPSW;
        Ap = (float4*)(gnb + (size_t)ta * Gn);
        a = Ap[l];
        c = ((const float4*)(gnb + (size_t)tb * Gn))[l];
    }
    float mx = (wi * a.x + wj * c.x) / tot;
    float my = (wi * a.y + wj * c.y) / tot;
    float mz = (wi * a.z + wj * c.z) / tot;
    float mw = (wi * a.w + wj * c.w) / tot;
    float ssq = mx * mx + my * my + mz * mz + mw * mw;
    ssq += __shfl_xor_sync(0xffffffffu, ssq, 8, 16);
    ssq += __shfl_xor_sync(0xffffffffu, ssq, 4, 16);
    ssq += __shfl_xor_sync(0xffffffffu, ssq, 2, 16);
    ssq += __shfl_xor_sync(0xffffffffu, ssq, 1, 16);
    if (valid) {
        float inv = 1.f / fmaxf(sqrtf(ssq), EPSN);
        float4 o; o.x = mx * inv; o.y = my * inv; o.z = mz * inv; o.w = mw * inv;
        Ap[l] = o;
        float fa = wi / tot, fb = wj / tot;
        float* cb = g_coef + b * Ln;
        for (int t = ta + l; t < tb; t += 16) cb[t] *= fa;
        for (int t = tb + l; t < tc; t += 16) cb[t] *= fb;
    }
}

// ---------------- K2c: recompute dirty-edge sims (full grid) ----------------
__global__ __launch_bounds__(256) void k_pairB()
{
    int b = blockIdx.y;
    int hw = blockIdx.x * 16 + (threadIdx.x >> 4);
    int l = threadIdx.x & 15;
    int ec = g_ec[b];
    bool valid = hw < ec;

    const float* gnb = g_gn + (size_t)b * Ln * Gn;
    int pos = 0;
    float d = 0.f;
    if (valid) {
        pos = g_edges[b][hw];
        int tA = g_slo[b][pos], tB = g_slo[b][pos + 1];
        float4 a = ((const float4*)(gnb + (size_t)tA * Gn))[l];
        float4 c = ((const float4*)(gnb + (size_t)tB * Gn))[l];
        d = a.x * c.x + a.y * c.y + a.z * c.z + a.w * c.w;
    }
    d += __shfl_down_sync(0xffffffffu, d, 8, 16);
    d += __shfl_down_sync(0xffffffffu, d, 4, 16);
    d += __shfl_down_sync(0xffffffffu, d, 2, 16);
    d += __shfl_down_sync(0xffffffffu, d, 1, 16);
    if (valid && l == 0) g_sim[b * Ln + pos] = d;
}

// ---------------- K3: apply plan (bandwidth-bound) ----------------
__global__ void k_apply(const float* __restrict__ x, const float* __restrict__ s,
                        float* __restrict__ out)
{
    int kslot = blockIdx.x;
    int chunk = blockIdx.y;
    int b = blockIdx.z;
    int lo = g_slo[b][kslot];
    int hi = g_slo[b][kslot + 1];
    int t4 = threadIdx.x;

    if (chunk == 0) {
        float4 acc = make_float4(0.f, 0.f, 0.f, 0.f);
#pragma unroll 2
        for (int t = lo; t < hi; t++) {
            float c = g_coef[b * Ln + t];
            float4 v = ((const float4*)(x + ((size_t)b * Ln + t) * Dn))[t4];
            acc.x += c * v.x; acc.y += c * v.y; acc.z += c * v.z; acc.w += c * v.w;
        }
        ((float4*)(out + ((size_t)b * Tn + kslot) * Dn))[t4] = acc;
    } else {
        int c0 = (chunk - 1) * 512;
        float4 acc = make_float4(0.f, 0.f, 0.f, 0.f);
#pragma unroll 2
        for (int t = lo; t < hi; t++) {
            float4 v = ((const float4*)(s + ((size_t)b * Ln + t) * Nn + c0))[t4];
            acc.x += v.x; acc.y += v.y; acc.z += v.z; acc.w += v.w;
        }
        ((float4*)(out + (size_t)Bn * Tn * Dn + ((size_t)b * Tn + kslot) * Nn + c0))[t4] = acc;
    }
}

// ---------------- launch ----------------
extern "C" void kernel_launch(void* const* d_in, const int* in_sizes, int n_in,
                              void* d_out, int out_size)
{
    const float* x = (const float*)d_in[0];
    const float* src = (const float*)d_in[1];
    const float* w = (const float*)d_in[2];
    float* out = (float*)d_out;

    k_init<<<8, 512>>>();                     // #0
    k_gn<<<Bn * Ln / 32, 256>>>(x, w);        // #1  (tiled GEMM)
    k_sim<<<dim3(128, Bn), 256>>>();          // #2
    for (int r = 0; r < RND; r++) {
        k_ctl<<<Bn, CT>>>();                  // #3 (round 1) -> ncu capture slot
        k_pairA<<<dim3(64, Bn), 256>>>();
        k_pairB<<<dim3(128, Bn), 256>>>();
    }
    dim3 g3(Tn, 1 + Nn / 512, Bn);
    k_apply<<<g3, 128>>>(x, src, out);
}